// round 6
// baseline (speedup 1.0000x reference)
#include <cuda_runtime.h>
#include <cuda_fp16.h>
#include <mma.h>
#include <stdint.h>
#include <limits.h>
using namespace nvcuda;

#define N_NODES 100000
#define N_EDGES 1600000
#define N_GRAPH 64
#define HID 128
#define IN_C 4
#define SCAN_CHUNK 512
#define SCAN_BLKS ((N_NODES + SCAN_CHUNK - 1) / SCAN_CHUNK)   // 196
#define N_PAD ((N_NODES + 127) & ~127)                        // 100096
#define N_SPLIT 50048                                          // 391 GEMM tiles

// ---------------- scratch ----------------
__device__ __half g_h16A[(size_t)N_PAD * HID];      // g0 -> g2
__device__ __half g_h16B[(size_t)N_PAD * HID];      // h2
__device__ int   g_csr[N_EDGES];
__device__ int   g_deg[N_NODES + 1];                // [N_NODES] = scan cursor
__device__ int   g_off[N_NODES];                    // start (pre-fill) -> end (post-fill)
__device__ float g_dinv[N_NODES];
__device__ int   g_cnt[N_GRAPH];
__device__ int   g_is64;

// ---------------- dtype detection ----------------
__global__ void k_detect(const int* ei32) {
    int t = threadIdx.x;
    int z = (ei32[2 * t + 1] == 0);
    unsigned m = __ballot_sync(0xFFFFFFFFu, z);
    __shared__ int ok[2];
    if ((t & 31) == 0) ok[t >> 5] = (m == 0xFFFFFFFFu);
    __syncthreads();
    if (t == 0) g_is64 = ok[0] & ok[1];
}

__device__ __forceinline__ int load_idx(const void* p, long long i) {
    if (g_is64) return (int)((const long long*)p)[i];
    return ((const int*)p)[i];
}

// ---------------- degree count (2 edges / thread) ----------------
__global__ void k_deg(const void* ei) {
    int t = blockIdx.x * blockDim.x + threadIdx.x;
    if (t >= N_EDGES / 2) return;
    int d0, d1;
    if (g_is64) {
        longlong2 p = __ldg(&((const longlong2*)ei)[N_EDGES / 2 + t]);
        d0 = (int)p.x; d1 = (int)p.y;
    } else {
        int2 p = __ldg(&((const int2*)ei)[N_EDGES / 2 + t]);
        d0 = p.x; d1 = p.y;
    }
    atomicAdd(&g_deg[d0], 1);
    atomicAdd(&g_deg[d1], 1);
}

// ---------------- fused scan: g_off[v]=segment start, g_dinv ----------------
__global__ void k_scan() {
    int tid = threadIdx.x;
    int i = blockIdx.x * SCAN_CHUNK + tid;
    int lane = tid & 31, wid = tid >> 5;          // 16 warps
    int d = (i < N_NODES) ? g_deg[i] : 0;
    int v = d;
    #pragma unroll
    for (int o = 1; o < 32; o <<= 1) {
        int t = __shfl_up_sync(0xFFFFFFFFu, v, o);
        if (lane >= o) v += t;
    }
    __shared__ int ws[16];
    __shared__ int base;
    if (lane == 31) ws[wid] = v;
    __syncthreads();
    if (wid == 0) {
        int s = (lane < 16) ? ws[lane] : 0;
        int sv = s;
        #pragma unroll
        for (int o = 1; o < 16; o <<= 1) {
            int t = __shfl_up_sync(0xFFFFFFFFu, sv, o);
            if (lane >= o) sv += t;
        }
        if (lane < 16) ws[lane] = sv - s;
        if (lane == 15) base = atomicAdd(&g_deg[N_NODES], sv);
    }
    __syncthreads();
    if (i < N_NODES) {
        g_off[i] = base + ws[wid] + (v - d);
        g_dinv[i] = rsqrtf((float)(d + 1));        // +1 self loop
    }
}

// ---------------- CSR fill (2 edges / thread): g_off start -> end ----------------
__global__ void k_fill(const void* ei) {
    int t = blockIdx.x * blockDim.x + threadIdx.x;
    if (t >= N_EDGES / 2) return;
    int s0, s1, d0, d1;
    if (g_is64) {
        longlong2 ps = __ldg(&((const longlong2*)ei)[t]);
        longlong2 pd = __ldg(&((const longlong2*)ei)[N_EDGES / 2 + t]);
        s0 = (int)ps.x; s1 = (int)ps.y; d0 = (int)pd.x; d1 = (int)pd.y;
    } else {
        int2 ps = __ldg(&((const int2*)ei)[t]);
        int2 pd = __ldg(&((const int2*)ei)[N_EDGES / 2 + t]);
        s0 = ps.x; s1 = ps.y; d0 = pd.x; d1 = pd.y;
    }
    int p0 = atomicAdd(&g_off[d0], 1);
    g_csr[p0] = s0;
    int p1 = atomicAdd(&g_off[d1], 1);
    g_csr[p1] = s1;
}

// ---------------- layer-1: g0 = fp16( dinv * (x @ W1) ), warp/node ----------------
__global__ void k_xw1(const float* __restrict__ x, const float* __restrict__ W1,
                      __half* __restrict__ outh) {
    int warp = (blockIdx.x * blockDim.x + threadIdx.x) >> 5;
    int lane = threadIdx.x & 31;
    int nwarps = (gridDim.x * blockDim.x) >> 5;
    const float4* W4 = (const float4*)W1;
    float4 w0 = __ldg(&W4[0 * 32 + lane]);
    float4 w1 = __ldg(&W4[1 * 32 + lane]);
    float4 w2 = __ldg(&W4[2 * 32 + lane]);
    float4 w3 = __ldg(&W4[3 * 32 + lane]);
    for (int vtx = warp; vtx < N_NODES; vtx += nwarps) {
        float xv = (lane < IN_C) ? __ldg(&x[vtx * IN_C + lane]) : 0.0f;
        float x0 = __shfl_sync(0xFFFFFFFFu, xv, 0);
        float x1 = __shfl_sync(0xFFFFFFFFu, xv, 1);
        float x2 = __shfl_sync(0xFFFFFFFFu, xv, 2);
        float x3 = __shfl_sync(0xFFFFFFFFu, xv, 3);
        float dv = g_dinv[vtx];
        float ax = dv * (x0 * w0.x + x1 * w1.x + x2 * w2.x + x3 * w3.x);
        float ay = dv * (x0 * w0.y + x1 * w1.y + x2 * w2.y + x3 * w3.y);
        float az = dv * (x0 * w0.z + x1 * w1.z + x2 * w2.z + x3 * w3.z);
        float aw = dv * (x0 * w0.w + x1 * w1.w + x2 * w2.w + x3 * w3.w);
        __half2 p0 = __floats2half2_rn(ax, ay);
        __half2 p1 = __floats2half2_rn(az, aw);
        uint2 u;
        u.x = *(const unsigned*)&p0;
        u.y = *(const unsigned*)&p1;
        ((uint2*)(outh + (size_t)vtx * HID))[lane] = u;
    }
}

// ---------------- gather core: accumulate in-edges + self into a[8] (per half-warp) ----------------
__device__ __forceinline__ void acc8(float* a, uint4 u) {
    float2 f0 = __half22float2(*(const __half2*)&u.x);
    float2 f1 = __half22float2(*(const __half2*)&u.y);
    float2 f2 = __half22float2(*(const __half2*)&u.z);
    float2 f3 = __half22float2(*(const __half2*)&u.w);
    a[0] += f0.x; a[1] += f0.y; a[2] += f1.x; a[3] += f1.y;
    a[4] += f2.x; a[5] += f2.y; a[6] += f3.x; a[7] += f3.y;
}

__device__ __forceinline__ void gather_core(const uint4* gin4, int v, int hf, int sub,
                                            int lane, float* a) {
    #pragma unroll
    for (int k = 0; k < 8; ++k) a[k] = 0.0f;
    int e = g_off[v];
    int j = e - g_deg[v] + hf;
    for (; j + 6 < e; j += 8) {
        int s0 = __ldg(&g_csr[j]);
        int s1 = __ldg(&g_csr[j + 2]);
        int s2 = __ldg(&g_csr[j + 4]);
        int s3 = __ldg(&g_csr[j + 6]);
        uint4 u0 = __ldg(&gin4[(size_t)s0 * 16 + sub]);
        uint4 u1 = __ldg(&gin4[(size_t)s1 * 16 + sub]);
        uint4 u2 = __ldg(&gin4[(size_t)s2 * 16 + sub]);
        uint4 u3 = __ldg(&gin4[(size_t)s3 * 16 + sub]);
        acc8(a, u0); acc8(a, u1); acc8(a, u2); acc8(a, u3);
    }
    for (; j < e; j += 2) {
        int s0 = __ldg(&g_csr[j]);
        uint4 u0 = __ldg(&gin4[(size_t)s0 * 16 + sub]);
        acc8(a, u0);
    }
    __syncwarp();
    #pragma unroll
    for (int k = 0; k < 8; ++k) a[k] += __shfl_xor_sync(0xFFFFFFFFu, a[k], 16);
    if (hf == 0) {
        uint4 us = __ldg(&gin4[(size_t)v * 16 + sub]);   // self loop
        acc8(a, us);
    }
}

// ---------------- gather-1: h2 = relu(dinv*agg + b), fp16 out, node range [v0, v0+nv) ----------------
__global__ void k_gather1(const __half* __restrict__ gin, const float* __restrict__ bias,
                          __half* __restrict__ gout, int v0, int nv) {
    int w = (blockIdx.x * blockDim.x + threadIdx.x) >> 5;
    int lane = threadIdx.x & 31;
    if (w >= nv) return;
    int v = v0 + w;
    int hf = lane >> 4, sub = lane & 15;
    const uint4* gin4 = (const uint4*)gin;
    float a[8];
    gather_core(gin4, v, hf, sub, lane, a);
    if (hf == 0) {
        float dv = g_dinv[v];
        const float4* b4 = (const float4*)bias;
        float4 bb0 = __ldg(&b4[sub * 2]);
        float4 bb1 = __ldg(&b4[sub * 2 + 1]);
        __half2 p0 = __floats2half2_rn(fmaxf(dv * a[0] + bb0.x, 0.0f),
                                       fmaxf(dv * a[1] + bb0.y, 0.0f));
        __half2 p1 = __floats2half2_rn(fmaxf(dv * a[2] + bb0.z, 0.0f),
                                       fmaxf(dv * a[3] + bb0.w, 0.0f));
        __half2 p2 = __floats2half2_rn(fmaxf(dv * a[4] + bb1.x, 0.0f),
                                       fmaxf(dv * a[5] + bb1.y, 0.0f));
        __half2 p3 = __floats2half2_rn(fmaxf(dv * a[6] + bb1.z, 0.0f),
                                       fmaxf(dv * a[7] + bb1.w, 0.0f));
        uint4 o;
        o.x = *(const unsigned*)&p0;
        o.y = *(const unsigned*)&p1;
        o.z = *(const unsigned*)&p2;
        o.w = *(const unsigned*)&p3;
        ((uint4*)gout)[(size_t)v * 16 + sub] = o;
    }
}

// ---------------- gather-2 fused with mean pool ----------------
// 8 nodes/block. Accumulate relu rows into smem by graph slot (batch sorted ->
// few distinct graphs per block), flush slot sums with global fp32 atomics.
__global__ void k_gather2_pool(const __half* __restrict__ gin, const float* __restrict__ bias,
                               const void* batch, float* __restrict__ outp) {
    __shared__ float s[8][HID];
    __shared__ int wb[8];
    __shared__ int sg[8];
    int wid = threadIdx.x >> 5, lane = threadIdx.x & 31;
    int hf = lane >> 4, sub = lane & 15;
    int v = blockIdx.x * 8 + wid;
    bool active = (v < N_NODES);
    const uint4* gin4 = (const uint4*)gin;
    float a[8];
    int b = -1;
    if (active) {
        gather_core(gin4, v, hf, sub, lane, a);
        b = load_idx(batch, v);
        if (hf == 0) {
            float dv = g_dinv[v];
            const float4* b4 = (const float4*)bias;
            float4 bb0 = __ldg(&b4[sub * 2]);
            float4 bb1 = __ldg(&b4[sub * 2 + 1]);
            a[0] = fmaxf(dv * a[0] + bb0.x, 0.0f);
            a[1] = fmaxf(dv * a[1] + bb0.y, 0.0f);
            a[2] = fmaxf(dv * a[2] + bb0.z, 0.0f);
            a[3] = fmaxf(dv * a[3] + bb0.w, 0.0f);
            a[4] = fmaxf(dv * a[4] + bb1.x, 0.0f);
            a[5] = fmaxf(dv * a[5] + bb1.y, 0.0f);
            a[6] = fmaxf(dv * a[6] + bb1.z, 0.0f);
            a[7] = fmaxf(dv * a[7] + bb1.w, 0.0f);
        }
    }
    if (lane == 0) wb[wid] = b;
    for (int i = threadIdx.x; i < 8 * HID; i += 256) ((float*)s)[i] = 0.0f;
    __syncthreads();
    // distinct-graph slots (batch sorted => wb nondecreasing over valid warps)
    int nslots = 0, myslot = -1, lastb = INT_MIN;
    #pragma unroll
    for (int k = 0; k < 8; ++k) {
        int bk = wb[k];
        if (bk < 0) break;
        if (bk != lastb) {
            if (threadIdx.x == 0) sg[nslots] = bk;
            nslots++;
            lastb = bk;
        }
        if (k == wid) myslot = nslots - 1;
    }
    if (active && hf == 0) {
        #pragma unroll
        for (int k = 0; k < 8; ++k)
            atomicAdd(&s[myslot][sub * 8 + k], a[k]);
    }
    if (active && lane == 0) atomicAdd(&g_cnt[b], 1);
    __syncthreads();
    for (int i = threadIdx.x; i < nslots * HID; i += 256) {
        int slot = i >> 7, c = i & 127;
        atomicAdd(&outp[sg[slot] * HID + c], s[slot][c]);
    }
}

// ---------------- tensor-core GEMM: g2 = fp16( dinv * (h2 @ W2) ), tile range ----------------
#define MM_PITCH 136
__global__ void k_h2w2_mma(const __half* __restrict__ hin, const float* __restrict__ W2,
                           __half* __restrict__ outh, int tile0, int tile1) {
    extern __shared__ __half smh[];
    __half* W2h = smh;                                   // [128][MM_PITCH] fp16
    float* stage = (float*)(smh + HID * MM_PITCH);       // [8][16][MM_PITCH] fp32
    int t = threadIdx.x;
    int warp = t >> 5, lane = t & 31;
    for (int i = t; i < HID * HID; i += 256) {
        int r = i >> 7, c = i & 127;
        W2h[r * MM_PITCH + c] = __float2half(W2[i]);
    }
    __syncthreads();

    float* st = stage + warp * 16 * MM_PITCH;
    for (int tile = tile0 + blockIdx.x; tile < tile1; tile += gridDim.x) {
        int row0 = tile * 128 + warp * 16;
        wmma::fragment<wmma::accumulator, 16, 16, 16, float> c[8];
        #pragma unroll
        for (int n = 0; n < 8; ++n) wmma::fill_fragment(c[n], 0.0f);
        #pragma unroll
        for (int k0 = 0; k0 < HID; k0 += 16) {
            wmma::fragment<wmma::matrix_a, 16, 16, 16, __half, wmma::row_major> a;
            wmma::load_matrix_sync(a, hin + (size_t)row0 * HID + k0, HID);
            #pragma unroll
            for (int n = 0; n < 8; ++n) {
                wmma::fragment<wmma::matrix_b, 16, 16, 16, __half, wmma::row_major> b;
                wmma::load_matrix_sync(b, W2h + k0 * MM_PITCH + n * 16, MM_PITCH);
                wmma::mma_sync(c[n], a, b, c[n]);
            }
        }
        #pragma unroll
        for (int n = 0; n < 8; ++n)
            wmma::store_matrix_sync(st + n * 16, c[n], MM_PITCH, wmma::mem_row_major);
        __syncwarp();
        #pragma unroll
        for (int r = 0; r < 16; ++r) {
            int row = row0 + r;
            if (row < N_NODES) {
                float dv = g_dinv[row];
                float4 v = *(const float4*)&st[r * MM_PITCH + lane * 4];
                __half2 p0 = __floats2half2_rn(dv * v.x, dv * v.y);
                __half2 p1 = __floats2half2_rn(dv * v.z, dv * v.w);
                uint2 u;
                u.x = *(const unsigned*)&p0;
                u.y = *(const unsigned*)&p1;
                *(uint2*)&outh[(size_t)row * HID + lane * 4] = u;
            }
        }
        __syncwarp();
    }
}

// ---------------- final divide by counts ----------------
__global__ void k_div(float* outp) {
    int i = blockIdx.x * blockDim.x + threadIdx.x;
    if (i >= N_GRAPH * HID) return;
    int g = i >> 7;
    outp[i] /= fmaxf((float)g_cnt[g], 1.0f);
}

// ---------------- launch ----------------
extern "C" void kernel_launch(void* const* d_in, const int* in_sizes, int n_in,
                              void* d_out, int out_size) {
    const float* x  = (const float*)d_in[0];
    const void*  ei = d_in[1];
    const void*  batch = d_in[2];
    const float* W1 = (const float*)d_in[3];
    const float* b1 = (const float*)d_in[4];
    const float* W2 = (const float*)d_in[5];
    const float* b2 = (const float*)d_in[6];
    float* out = (float*)d_out;

    void* degp;  cudaGetSymbolAddress(&degp, g_deg);
    void* cntp;  cudaGetSymbolAddress(&cntp, g_cnt);
    void* h16Ap; cudaGetSymbolAddress(&h16Ap, g_h16A);
    void* h16Bp; cudaGetSymbolAddress(&h16Bp, g_h16B);

    static cudaStream_t sB = nullptr;
    static cudaEvent_t evScan, evXw1, evG1a, evG1b, evMM;
    static int inited = 0;
    const int mma_smem = HID * MM_PITCH * sizeof(__half) + 8 * 16 * MM_PITCH * sizeof(float);
    if (!inited) {
        cudaFuncSetAttribute(k_h2w2_mma, cudaFuncAttributeMaxDynamicSharedMemorySize, mma_smem);
        cudaStreamCreateWithFlags(&sB, cudaStreamNonBlocking);
        cudaEventCreateWithFlags(&evScan, cudaEventDisableTiming);
        cudaEventCreateWithFlags(&evXw1, cudaEventDisableTiming);
        cudaEventCreateWithFlags(&evG1a, cudaEventDisableTiming);
        cudaEventCreateWithFlags(&evG1b, cudaEventDisableTiming);
        cudaEventCreateWithFlags(&evMM, cudaEventDisableTiming);
        inited = 1;
    }

    // ---- stream 0: CSR build ----
    k_detect<<<1, 64>>>((const int*)ei);
    cudaMemsetAsync(degp, 0, (N_NODES + 1) * sizeof(int));
    cudaMemsetAsync(cntp, 0, N_GRAPH * sizeof(int));
    cudaMemsetAsync(out, 0, N_GRAPH * HID * sizeof(float));

    const int EB2 = (N_EDGES / 2 + 255) / 256;
    k_deg<<<EB2, 256>>>(ei);
    k_scan<<<SCAN_BLKS, SCAN_CHUNK>>>();
    cudaEventRecord(evScan, 0);

    // ---- stream B: xw1 (needs dinv) overlapped with fill ----
    cudaStreamWaitEvent(sB, evScan, 0);
    k_xw1<<<256, 256, 0, sB>>>(x, W1, (__half*)h16Ap);
    cudaEventRecord(evXw1, sB);

    k_fill<<<EB2, 256>>>(ei);
    cudaStreamWaitEvent(0, evXw1, 0);

    // ---- gather-1 in 2 chunks; GEMM chunks pipeline on stream B ----
    const int NV0 = N_SPLIT, NV1 = N_NODES - N_SPLIT;
    k_gather1<<<(NV0 * 32 + 255) / 256, 256>>>((__half*)h16Ap, b1, (__half*)h16Bp, 0, NV0);
    cudaEventRecord(evG1a, 0);
    k_gather1<<<(NV1 * 32 + 255) / 256, 256>>>((__half*)h16Ap, b1, (__half*)h16Bp, N_SPLIT, NV1);
    cudaEventRecord(evG1b, 0);

    cudaStreamWaitEvent(sB, evG1a, 0);
    k_h2w2_mma<<<296, 256, mma_smem, sB>>>((__half*)h16Bp, W2, (__half*)h16Ap, 0, N_SPLIT / 128);
    cudaStreamWaitEvent(sB, evG1b, 0);
    k_h2w2_mma<<<296, 256, mma_smem, sB>>>((__half*)h16Bp, W2, (__half*)h16Ap,
                                           N_SPLIT / 128, N_PAD / 128);
    cudaEventRecord(evMM, sB);
    cudaStreamWaitEvent(0, evMM, 0);

    // ---- gather-2 fused with mean pool, then divide ----
    k_gather2_pool<<<(N_NODES + 7) / 8, 256>>>((__half*)h16Ap, b2, batch, out);
    k_div<<<(N_GRAPH * HID + 255) / 256, 256>>>(out);
}

// round 7
// speedup vs baseline: 1.0384x; 1.0384x over previous
#include <cuda_runtime.h>
#include <cuda_fp16.h>
#include <mma.h>
#include <stdint.h>
#include <limits.h>
using namespace nvcuda;

#define N_NODES 100000
#define N_EDGES 1600000
#define N_GRAPH 64
#define HID 128
#define IN_C 4
#define SCAN_CHUNK 512
#define SCAN_BLKS ((N_NODES + SCAN_CHUNK - 1) / SCAN_CHUNK)   // 196
#define N_PAD ((N_NODES + 127) & ~127)                        // 100096

// ---------------- scratch ----------------
__device__ __half g_h16A[(size_t)N_PAD * HID];      // g0 -> g2
__device__ __half g_h16B[(size_t)N_PAD * HID];      // h2
__device__ int   g_csr[N_EDGES];
__device__ int   g_deg[N_NODES + 1];                // [N_NODES] = scan cursor
__device__ int   g_off[N_NODES];                    // start (pre-fill) -> end (post-fill)
__device__ float g_dinv[N_NODES];
__device__ int   g_cnt[N_GRAPH];
__device__ int   g_is64;

// ---------------- dtype detection ----------------
__global__ void k_detect(const int* ei32) {
    int t = threadIdx.x;
    int z = (ei32[2 * t + 1] == 0);
    unsigned m = __ballot_sync(0xFFFFFFFFu, z);
    __shared__ int ok[2];
    if ((t & 31) == 0) ok[t >> 5] = (m == 0xFFFFFFFFu);
    __syncthreads();
    if (t == 0) g_is64 = ok[0] & ok[1];
}

__device__ __forceinline__ int load_idx(const void* p, long long i) {
    if (g_is64) return (int)((const long long*)p)[i];
    return ((const int*)p)[i];
}

// ---------------- degree count (2 edges / thread) ----------------
__global__ void k_deg(const void* ei) {
    int t = blockIdx.x * blockDim.x + threadIdx.x;
    if (t >= N_EDGES / 2) return;
    int d0, d1;
    if (g_is64) {
        longlong2 p = __ldg(&((const longlong2*)ei)[N_EDGES / 2 + t]);
        d0 = (int)p.x; d1 = (int)p.y;
    } else {
        int2 p = __ldg(&((const int2*)ei)[N_EDGES / 2 + t]);
        d0 = p.x; d1 = p.y;
    }
    atomicAdd(&g_deg[d0], 1);
    atomicAdd(&g_deg[d1], 1);
}

// ---------------- fused scan: g_off[v]=segment start, g_dinv ----------------
__global__ void k_scan() {
    int tid = threadIdx.x;
    int i = blockIdx.x * SCAN_CHUNK + tid;
    int lane = tid & 31, wid = tid >> 5;          // 16 warps
    int d = (i < N_NODES) ? g_deg[i] : 0;
    int v = d;
    #pragma unroll
    for (int o = 1; o < 32; o <<= 1) {
        int t = __shfl_up_sync(0xFFFFFFFFu, v, o);
        if (lane >= o) v += t;
    }
    __shared__ int ws[16];
    __shared__ int base;
    if (lane == 31) ws[wid] = v;
    __syncthreads();
    if (wid == 0) {
        int s = (lane < 16) ? ws[lane] : 0;
        int sv = s;
        #pragma unroll
        for (int o = 1; o < 16; o <<= 1) {
            int t = __shfl_up_sync(0xFFFFFFFFu, sv, o);
            if (lane >= o) sv += t;
        }
        if (lane < 16) ws[lane] = sv - s;
        if (lane == 15) base = atomicAdd(&g_deg[N_NODES], sv);
    }
    __syncthreads();
    if (i < N_NODES) {
        g_off[i] = base + ws[wid] + (v - d);
        g_dinv[i] = rsqrtf((float)(d + 1));        // +1 self loop
    }
}

// ---------------- CSR fill (2 edges / thread): g_off start -> end ----------------
__global__ void k_fill(const void* ei) {
    int t = blockIdx.x * blockDim.x + threadIdx.x;
    if (t >= N_EDGES / 2) return;
    int s0, s1, d0, d1;
    if (g_is64) {
        longlong2 ps = __ldg(&((const longlong2*)ei)[t]);
        longlong2 pd = __ldg(&((const longlong2*)ei)[N_EDGES / 2 + t]);
        s0 = (int)ps.x; s1 = (int)ps.y; d0 = (int)pd.x; d1 = (int)pd.y;
    } else {
        int2 ps = __ldg(&((const int2*)ei)[t]);
        int2 pd = __ldg(&((const int2*)ei)[N_EDGES / 2 + t]);
        s0 = ps.x; s1 = ps.y; d0 = pd.x; d1 = pd.y;
    }
    int p0 = atomicAdd(&g_off[d0], 1);
    g_csr[p0] = s0;
    int p1 = atomicAdd(&g_off[d1], 1);
    g_csr[p1] = s1;
}

// ---------------- layer-1: g0 = fp16( dinv * (x @ W1) ), warp/node ----------------
__global__ void k_xw1(const float* __restrict__ x, const float* __restrict__ W1,
                      __half* __restrict__ outh) {
    int warp = (blockIdx.x * blockDim.x + threadIdx.x) >> 5;
    int lane = threadIdx.x & 31;
    int nwarps = (gridDim.x * blockDim.x) >> 5;
    const float4* W4 = (const float4*)W1;
    float4 w0 = __ldg(&W4[0 * 32 + lane]);
    float4 w1 = __ldg(&W4[1 * 32 + lane]);
    float4 w2 = __ldg(&W4[2 * 32 + lane]);
    float4 w3 = __ldg(&W4[3 * 32 + lane]);
    for (int vtx = warp; vtx < N_NODES; vtx += nwarps) {
        float xv = (lane < IN_C) ? __ldg(&x[vtx * IN_C + lane]) : 0.0f;
        float x0 = __shfl_sync(0xFFFFFFFFu, xv, 0);
        float x1 = __shfl_sync(0xFFFFFFFFu, xv, 1);
        float x2 = __shfl_sync(0xFFFFFFFFu, xv, 2);
        float x3 = __shfl_sync(0xFFFFFFFFu, xv, 3);
        float dv = g_dinv[vtx];
        float ax = dv * (x0 * w0.x + x1 * w1.x + x2 * w2.x + x3 * w3.x);
        float ay = dv * (x0 * w0.y + x1 * w1.y + x2 * w2.y + x3 * w3.y);
        float az = dv * (x0 * w0.z + x1 * w1.z + x2 * w2.z + x3 * w3.z);
        float aw = dv * (x0 * w0.w + x1 * w1.w + x2 * w2.w + x3 * w3.w);
        __half2 p0 = __floats2half2_rn(ax, ay);
        __half2 p1 = __floats2half2_rn(az, aw);
        uint2 u;
        u.x = *(const unsigned*)&p0;
        u.y = *(const unsigned*)&p1;
        ((uint2*)(outh + (size_t)vtx * HID))[lane] = u;
    }
}

// ---------------- gather core: accumulate in-edges + self into a[8] (per half-warp) ----------------
__device__ __forceinline__ void acc8(float* a, uint4 u) {
    float2 f0 = __half22float2(*(const __half2*)&u.x);
    float2 f1 = __half22float2(*(const __half2*)&u.y);
    float2 f2 = __half22float2(*(const __half2*)&u.z);
    float2 f3 = __half22float2(*(const __half2*)&u.w);
    a[0] += f0.x; a[1] += f0.y; a[2] += f1.x; a[3] += f1.y;
    a[4] += f2.x; a[5] += f2.y; a[6] += f3.x; a[7] += f3.y;
}

__device__ __forceinline__ void gather_core(const uint4* gin4, int v, int hf, int sub,
                                            float* a) {
    #pragma unroll
    for (int k = 0; k < 8; ++k) a[k] = 0.0f;
    int e = g_off[v];
    int j = e - g_deg[v] + hf;
    for (; j + 6 < e; j += 8) {
        int s0 = __ldg(&g_csr[j]);
        int s1 = __ldg(&g_csr[j + 2]);
        int s2 = __ldg(&g_csr[j + 4]);
        int s3 = __ldg(&g_csr[j + 6]);
        uint4 u0 = __ldg(&gin4[(size_t)s0 * 16 + sub]);
        uint4 u1 = __ldg(&gin4[(size_t)s1 * 16 + sub]);
        uint4 u2 = __ldg(&gin4[(size_t)s2 * 16 + sub]);
        uint4 u3 = __ldg(&gin4[(size_t)s3 * 16 + sub]);
        acc8(a, u0); acc8(a, u1); acc8(a, u2); acc8(a, u3);
    }
    for (; j < e; j += 2) {
        int s0 = __ldg(&g_csr[j]);
        uint4 u0 = __ldg(&gin4[(size_t)s0 * 16 + sub]);
        acc8(a, u0);
    }
    __syncwarp();
    #pragma unroll
    for (int k = 0; k < 8; ++k) a[k] += __shfl_xor_sync(0xFFFFFFFFu, a[k], 16);
    if (hf == 0) {
        uint4 us = __ldg(&gin4[(size_t)v * 16 + sub]);   // self loop
        acc8(a, us);
    }
}

// ---------------- gather-1: h2 = relu(dinv*agg + b), fp16 out ----------------
__global__ void k_gather1(const __half* __restrict__ gin, const float* __restrict__ bias,
                          __half* __restrict__ gout) {
    int v = (blockIdx.x * blockDim.x + threadIdx.x) >> 5;
    int lane = threadIdx.x & 31;
    if (v >= N_NODES) return;
    int hf = lane >> 4, sub = lane & 15;
    const uint4* gin4 = (const uint4*)gin;
    float a[8];
    gather_core(gin4, v, hf, sub, a);
    if (hf == 0) {
        float dv = g_dinv[v];
        const float4* b4 = (const float4*)bias;
        float4 bb0 = __ldg(&b4[sub * 2]);
        float4 bb1 = __ldg(&b4[sub * 2 + 1]);
        __half2 p0 = __floats2half2_rn(fmaxf(dv * a[0] + bb0.x, 0.0f),
                                       fmaxf(dv * a[1] + bb0.y, 0.0f));
        __half2 p1 = __floats2half2_rn(fmaxf(dv * a[2] + bb0.z, 0.0f),
                                       fmaxf(dv * a[3] + bb0.w, 0.0f));
        __half2 p2 = __floats2half2_rn(fmaxf(dv * a[4] + bb1.x, 0.0f),
                                       fmaxf(dv * a[5] + bb1.y, 0.0f));
        __half2 p3 = __floats2half2_rn(fmaxf(dv * a[6] + bb1.z, 0.0f),
                                       fmaxf(dv * a[7] + bb1.w, 0.0f));
        uint4 o;
        o.x = *(const unsigned*)&p0;
        o.y = *(const unsigned*)&p1;
        o.z = *(const unsigned*)&p2;
        o.w = *(const unsigned*)&p3;
        ((uint4*)gout)[(size_t)v * 16 + sub] = o;
    }
}

// ---------------- gather-2 fused with mean pool ----------------
// 8 nodes/block; accumulate relu rows into per-graph smem slots (batch sorted),
// flush slot sums with global fp32 atomics. No h3 buffer at all.
__global__ void k_gather2_pool(const __half* __restrict__ gin, const float* __restrict__ bias,
                               const void* batch, float* __restrict__ outp) {
    __shared__ float s[8][HID];
    __shared__ int wb[8];
    __shared__ int sg[8];
    int wid = threadIdx.x >> 5, lane = threadIdx.x & 31;
    int hf = lane >> 4, sub = lane & 15;
    int v = blockIdx.x * 8 + wid;
    bool active = (v < N_NODES);
    const uint4* gin4 = (const uint4*)gin;
    float a[8];
    int b = -1;
    if (active) {
        gather_core(gin4, v, hf, sub, a);
        b = load_idx(batch, v);
        if (hf == 0) {
            float dv = g_dinv[v];
            const float4* b4 = (const float4*)bias;
            float4 bb0 = __ldg(&b4[sub * 2]);
            float4 bb1 = __ldg(&b4[sub * 2 + 1]);
            a[0] = fmaxf(dv * a[0] + bb0.x, 0.0f);
            a[1] = fmaxf(dv * a[1] + bb0.y, 0.0f);
            a[2] = fmaxf(dv * a[2] + bb0.z, 0.0f);
            a[3] = fmaxf(dv * a[3] + bb0.w, 0.0f);
            a[4] = fmaxf(dv * a[4] + bb1.x, 0.0f);
            a[5] = fmaxf(dv * a[5] + bb1.y, 0.0f);
            a[6] = fmaxf(dv * a[6] + bb1.z, 0.0f);
            a[7] = fmaxf(dv * a[7] + bb1.w, 0.0f);
        }
    }
    if (lane == 0) wb[wid] = b;
    for (int i = threadIdx.x; i < 8 * HID; i += 256) ((float*)s)[i] = 0.0f;
    __syncthreads();
    // distinct-graph slots (batch sorted => wb nondecreasing over valid warps)
    int nslots = 0, myslot = -1, lastb = INT_MIN;
    #pragma unroll
    for (int k = 0; k < 8; ++k) {
        int bk = wb[k];
        if (bk < 0) break;
        if (bk != lastb) {
            if (threadIdx.x == 0) sg[nslots] = bk;
            nslots++;
            lastb = bk;
        }
        if (k == wid) myslot = nslots - 1;
    }
    if (active && hf == 0) {
        #pragma unroll
        for (int k = 0; k < 8; ++k)
            atomicAdd(&s[myslot][sub * 8 + k], a[k]);
    }
    if (active && lane == 0) atomicAdd(&g_cnt[b], 1);
    __syncthreads();
    for (int i = threadIdx.x; i < nslots * HID; i += 256) {
        int slot = i >> 7, c = i & 127;
        atomicAdd(&outp[sg[slot] * HID + c], s[slot][c]);
    }
}

// ---------------- tensor-core GEMM: g2 = fp16( dinv * (h2 @ W2) ) ----------------
#define MM_PITCH 136
__global__ void k_h2w2_mma(const __half* __restrict__ hin, const float* __restrict__ W2,
                           __half* __restrict__ outh) {
    extern __shared__ __half smh[];
    __half* W2h = smh;                                   // [128][MM_PITCH] fp16
    float* stage = (float*)(smh + HID * MM_PITCH);       // [8][16][MM_PITCH] fp32
    int t = threadIdx.x;
    int warp = t >> 5, lane = t & 31;
    for (int i = t; i < HID * HID; i += 256) {
        int r = i >> 7, c = i & 127;
        W2h[r * MM_PITCH + c] = __float2half(W2[i]);
    }
    __syncthreads();

    float* st = stage + warp * 16 * MM_PITCH;
    const int ntiles = N_PAD / 128;   // 782
    for (int tile = blockIdx.x; tile < ntiles; tile += gridDim.x) {
        int row0 = tile * 128 + warp * 16;
        wmma::fragment<wmma::accumulator, 16, 16, 16, float> c[8];
        #pragma unroll
        for (int n = 0; n < 8; ++n) wmma::fill_fragment(c[n], 0.0f);
        #pragma unroll
        for (int k0 = 0; k0 < HID; k0 += 16) {
            wmma::fragment<wmma::matrix_a, 16, 16, 16, __half, wmma::row_major> a;
            wmma::load_matrix_sync(a, hin + (size_t)row0 * HID + k0, HID);
            #pragma unroll
            for (int n = 0; n < 8; ++n) {
                wmma::fragment<wmma::matrix_b, 16, 16, 16, __half, wmma::row_major> b;
                wmma::load_matrix_sync(b, W2h + k0 * MM_PITCH + n * 16, MM_PITCH);
                wmma::mma_sync(c[n], a, b, c[n]);
            }
        }
        #pragma unroll
        for (int n = 0; n < 8; ++n)
            wmma::store_matrix_sync(st + n * 16, c[n], MM_PITCH, wmma::mem_row_major);
        __syncwarp();
        #pragma unroll
        for (int r = 0; r < 16; ++r) {
            int row = row0 + r;
            if (row < N_NODES) {
                float dv = g_dinv[row];
                float4 v = *(const float4*)&st[r * MM_PITCH + lane * 4];
                __half2 p0 = __floats2half2_rn(dv * v.x, dv * v.y);
                __half2 p1 = __floats2half2_rn(dv * v.z, dv * v.w);
                uint2 u;
                u.x = *(const unsigned*)&p0;
                u.y = *(const unsigned*)&p1;
                *(uint2*)&outh[(size_t)row * HID + lane * 4] = u;
            }
        }
        __syncwarp();
    }
}

// ---------------- final divide by counts ----------------
__global__ void k_div(float* outp) {
    int i = blockIdx.x * blockDim.x + threadIdx.x;
    if (i >= N_GRAPH * HID) return;
    int g = i >> 7;
    outp[i] /= fmaxf((float)g_cnt[g], 1.0f);
}

// ---------------- launch (single stream, linear chain) ----------------
extern "C" void kernel_launch(void* const* d_in, const int* in_sizes, int n_in,
                              void* d_out, int out_size) {
    const float* x  = (const float*)d_in[0];
    const void*  ei = d_in[1];
    const void*  batch = d_in[2];
    const float* W1 = (const float*)d_in[3];
    const float* b1 = (const float*)d_in[4];
    const float* W2 = (const float*)d_in[5];
    const float* b2 = (const float*)d_in[6];
    float* out = (float*)d_out;

    void* degp;  cudaGetSymbolAddress(&degp, g_deg);
    void* cntp;  cudaGetSymbolAddress(&cntp, g_cnt);
    void* h16Ap; cudaGetSymbolAddress(&h16Ap, g_h16A);
    void* h16Bp; cudaGetSymbolAddress(&h16Bp, g_h16B);

    static int smem_set = 0;
    const int mma_smem = HID * MM_PITCH * sizeof(__half) + 8 * 16 * MM_PITCH * sizeof(float);
    if (!smem_set) {
        cudaFuncSetAttribute(k_h2w2_mma, cudaFuncAttributeMaxDynamicSharedMemorySize, mma_smem);
        smem_set = 1;
    }

    k_detect<<<1, 64>>>((const int*)ei);
    cudaMemsetAsync(degp, 0, (N_NODES + 1) * sizeof(int));
    cudaMemsetAsync(cntp, 0, N_GRAPH * sizeof(int));
    cudaMemsetAsync(out, 0, N_GRAPH * HID * sizeof(float));

    const int EB2 = (N_EDGES / 2 + 255) / 256;
    k_deg<<<EB2, 256>>>(ei);
    k_scan<<<SCAN_BLKS, SCAN_CHUNK>>>();
    k_fill<<<EB2, 256>>>(ei);

    k_xw1<<<592, 256>>>(x, W1, (__half*)h16Ap);                                        // g0 -> A
    k_gather1<<<(N_NODES * 32 + 255) / 256, 256>>>((__half*)h16Ap, b1, (__half*)h16Bp); // h2 -> B
    k_h2w2_mma<<<296, 256, mma_smem>>>((__half*)h16Bp, W2, (__half*)h16Ap);            // g2 -> A
    k_gather2_pool<<<(N_NODES + 7) / 8, 256>>>((__half*)h16Ap, b2, batch, out);        // pool
    k_div<<<(N_GRAPH * HID + 255) / 256, 256>>>(out);
}

// round 9
// speedup vs baseline: 1.4371x; 1.3840x over previous
#include <cuda_runtime.h>
#include <cuda_fp16.h>
#include <mma.h>
#include <stdint.h>
using namespace nvcuda;

#define N_NODES 100000
#define N_EDGES 1600000
#define N_GRAPH 64
#define HID 128
#define IN_C 4
#define ELL_CAP 64
#define N_PAD ((N_NODES + 127) & ~127)   // 100096

// ---------------- scratch ----------------
__device__ __half g_h16A[(size_t)N_PAD * HID];    // h2, then h3
__device__ __half g_h16B[(size_t)N_PAD * HID];    // g2
__device__ int    g_ell[(size_t)N_NODES * ELL_CAP];  // 25.6 MB
__device__ int    g_cnt[N_NODES];                 // in-degree (atomic cursor)
__device__ float  g_dinv[N_NODES];
__device__ uint2  g_p[N_NODES];                   // fp16x4: dinv*x
__device__ int    g_is64;

// ---------------- dtype detection ----------------
__global__ void k_detect(const int* ei32) {
    int t = threadIdx.x;
    int z = (ei32[2 * t + 1] == 0);
    unsigned m = __ballot_sync(0xFFFFFFFFu, z);
    __shared__ int ok[2];
    if ((t & 31) == 0) ok[t >> 5] = (m == 0xFFFFFFFFu);
    __syncthreads();
    if (t == 0) g_is64 = ok[0] & ok[1];
}

__device__ __forceinline__ int load_idx(const void* p, long long i) {
    if (g_is64) return (int)((const long long*)p)[i];
    return ((const int*)p)[i];
}

// ---------------- single-pass ELL build (4 edges / thread) ----------------
__global__ void k_fill_ell(const void* ei) {
    int t = blockIdx.x * blockDim.x + threadIdx.x;
    if (t >= N_EDGES / 4) return;
    int s[4], d[4];
    if (g_is64) {
        const longlong2* p64 = (const longlong2*)ei;
        longlong2 ps0 = __ldg(&p64[2 * t]);
        longlong2 ps1 = __ldg(&p64[2 * t + 1]);
        longlong2 pd0 = __ldg(&p64[N_EDGES / 2 + 2 * t]);
        longlong2 pd1 = __ldg(&p64[N_EDGES / 2 + 2 * t + 1]);
        s[0] = (int)ps0.x; s[1] = (int)ps0.y; s[2] = (int)ps1.x; s[3] = (int)ps1.y;
        d[0] = (int)pd0.x; d[1] = (int)pd0.y; d[2] = (int)pd1.x; d[3] = (int)pd1.y;
    } else {
        const int4* p32 = (const int4*)ei;
        int4 ps = __ldg(&p32[t]);
        int4 pd = __ldg(&p32[N_EDGES / 4 + t]);
        s[0] = ps.x; s[1] = ps.y; s[2] = ps.z; s[3] = ps.w;
        d[0] = pd.x; d[1] = pd.y; d[2] = pd.z; d[3] = pd.w;
    }
    #pragma unroll
    for (int k = 0; k < 4; ++k) {
        int pos = atomicAdd(&g_cnt[d[k]], 1);
        if (pos < ELL_CAP) g_ell[(size_t)d[k] * ELL_CAP + pos] = s[k];
    }
}

// ---------------- pre: dinv + p = fp16x4(dinv * x) ----------------
__global__ void k_pre(const float* __restrict__ x) {
    int v = blockIdx.x * blockDim.x + threadIdx.x;
    if (v >= N_NODES) return;
    float dv = rsqrtf((float)(g_cnt[v] + 1));   // +1 self loop
    g_dinv[v] = dv;
    float4 xv = __ldg(&((const float4*)x)[v]);
    __half2 p0 = __floats2half2_rn(dv * xv.x, dv * xv.y);
    __half2 p1 = __floats2half2_rn(dv * xv.z, dv * xv.w);
    uint2 u;
    u.x = *(const unsigned*)&p0;
    u.y = *(const unsigned*)&p1;
    g_p[v] = u;
}

// ---------------- layer 1: gather 4-wide p, then @W1 + b1, relu -> h2 fp16 ----------------
// warp per node; post-aggregation transform with W1 columns in registers.
__global__ void k_layer1(const float* __restrict__ W1, const float* __restrict__ b1,
                         __half* __restrict__ outh) {
    int warp = (blockIdx.x * blockDim.x + threadIdx.x) >> 5;
    int lane = threadIdx.x & 31;
    int nwarps = (gridDim.x * blockDim.x) >> 5;
    const float4* W4 = (const float4*)W1;        // row k, cols 4lane..4lane+3
    float4 w0 = __ldg(&W4[0 * 32 + lane]);
    float4 w1 = __ldg(&W4[1 * 32 + lane]);
    float4 w2 = __ldg(&W4[2 * 32 + lane]);
    float4 w3 = __ldg(&W4[3 * 32 + lane]);
    float4 bb = __ldg(&((const float4*)b1)[lane]);
    for (int v = warp; v < N_NODES; v += nwarps) {
        int deg = min(g_cnt[v], ELL_CAP);
        const int* row = g_ell + (size_t)v * ELL_CAP;
        float a0 = 0.0f, a1 = 0.0f, a2 = 0.0f, a3 = 0.0f;
        for (int j = lane; j < deg; j += 32) {
            int sidx = __ldg(&row[j]);
            uint2 u = __ldg(&g_p[sidx]);
            float2 f0 = __half22float2(*(const __half2*)&u.x);
            float2 f1 = __half22float2(*(const __half2*)&u.y);
            a0 += f0.x; a1 += f0.y; a2 += f1.x; a3 += f1.y;
        }
        #pragma unroll
        for (int o = 16; o > 0; o >>= 1) {
            a0 += __shfl_xor_sync(0xFFFFFFFFu, a0, o);
            a1 += __shfl_xor_sync(0xFFFFFFFFu, a1, o);
            a2 += __shfl_xor_sync(0xFFFFFFFFu, a2, o);
            a3 += __shfl_xor_sync(0xFFFFFFFFu, a3, o);
        }
        uint2 us = g_p[v];                         // self loop
        float2 s0 = __half22float2(*(const __half2*)&us.x);
        float2 s1 = __half22float2(*(const __half2*)&us.y);
        float dv = g_dinv[v];
        a0 = dv * (a0 + s0.x);
        a1 = dv * (a1 + s0.y);
        a2 = dv * (a2 + s1.x);
        a3 = dv * (a3 + s1.y);
        float o0 = fmaxf(a0 * w0.x + a1 * w1.x + a2 * w2.x + a3 * w3.x + bb.x, 0.0f);
        float o1 = fmaxf(a0 * w0.y + a1 * w1.y + a2 * w2.y + a3 * w3.y + bb.y, 0.0f);
        float o2 = fmaxf(a0 * w0.z + a1 * w1.z + a2 * w2.z + a3 * w3.z + bb.z, 0.0f);
        float o3 = fmaxf(a0 * w0.w + a1 * w1.w + a2 * w2.w + a3 * w3.w + bb.w, 0.0f);
        __half2 p0 = __floats2half2_rn(o0, o1);
        __half2 p1 = __floats2half2_rn(o2, o3);
        uint2 u;
        u.x = *(const unsigned*)&p0;
        u.y = *(const unsigned*)&p1;
        ((uint2*)(outh + (size_t)v * HID))[lane] = u;
    }
}

// ---------------- tensor-core GEMM: g2 = fp16( dinv * (h2 @ W2) ) ----------------
#define MM_PITCH 136
__global__ void k_h2w2_mma(const __half* __restrict__ hin, const float* __restrict__ W2,
                           __half* __restrict__ outh) {
    extern __shared__ __half smh[];
    __half* W2h = smh;                                   // [128][MM_PITCH] fp16
    float* stage = (float*)(smh + HID * MM_PITCH);       // [8][16][MM_PITCH] fp32
    int t = threadIdx.x;
    int warp = t >> 5, lane = t & 31;
    for (int i = t; i < HID * HID; i += 256) {
        int r = i >> 7, c = i & 127;
        W2h[r * MM_PITCH + c] = __float2half(W2[i]);
    }
    __syncthreads();

    float* st = stage + warp * 16 * MM_PITCH;
    const int ntiles = N_PAD / 128;   // 782
    for (int tile = blockIdx.x; tile < ntiles; tile += gridDim.x) {
        int row0 = tile * 128 + warp * 16;
        wmma::fragment<wmma::accumulator, 16, 16, 16, float> c[8];
        #pragma unroll
        for (int n = 0; n < 8; ++n) wmma::fill_fragment(c[n], 0.0f);
        #pragma unroll
        for (int k0 = 0; k0 < HID; k0 += 16) {
            wmma::fragment<wmma::matrix_a, 16, 16, 16, __half, wmma::row_major> a;
            wmma::load_matrix_sync(a, hin + (size_t)row0 * HID + k0, HID);
            #pragma unroll
            for (int n = 0; n < 8; ++n) {
                wmma::fragment<wmma::matrix_b, 16, 16, 16, __half, wmma::row_major> b;
                wmma::load_matrix_sync(b, W2h + k0 * MM_PITCH + n * 16, MM_PITCH);
                wmma::mma_sync(c[n], a, b, c[n]);
            }
        }
        #pragma unroll
        for (int n = 0; n < 8; ++n)
            wmma::store_matrix_sync(st + n * 16, c[n], MM_PITCH, wmma::mem_row_major);
        __syncwarp();
        #pragma unroll
        for (int r = 0; r < 16; ++r) {
            int row = row0 + r;
            if (row < N_NODES) {
                float dv = g_dinv[row];
                float4 v = *(const float4*)&st[r * MM_PITCH + lane * 4];
                __half2 p0 = __floats2half2_rn(dv * v.x, dv * v.y);
                __half2 p1 = __floats2half2_rn(dv * v.z, dv * v.w);
                uint2 u;
                u.x = *(const unsigned*)&p0;
                u.y = *(const unsigned*)&p1;
                *(uint2*)&outh[(size_t)row * HID + lane * 4] = u;
            }
        }
        __syncwarp();
    }
}

// ---------------- layer-2 gather: h3 = relu(dinv*agg(g2) + b2), fp16 out ----------------
__device__ __forceinline__ void acc8(float* a, uint4 u) {
    float2 f0 = __half22float2(*(const __half2*)&u.x);
    float2 f1 = __half22float2(*(const __half2*)&u.y);
    float2 f2 = __half22float2(*(const __half2*)&u.z);
    float2 f3 = __half22float2(*(const __half2*)&u.w);
    a[0] += f0.x; a[1] += f0.y; a[2] += f1.x; a[3] += f1.y;
    a[4] += f2.x; a[5] += f2.y; a[6] += f3.x; a[7] += f3.y;
}

__global__ void k_gather2(const __half* __restrict__ gin, const float* __restrict__ bias,
                          __half* __restrict__ gout) {
    int v = (blockIdx.x * blockDim.x + threadIdx.x) >> 5;
    int lane = threadIdx.x & 31;
    if (v >= N_NODES) return;
    int hf = lane >> 4, sub = lane & 15;
    const uint4* gin4 = (const uint4*)gin;     // 16 uint4 per node row
    float a[8];
    #pragma unroll
    for (int k = 0; k < 8; ++k) a[k] = 0.0f;
    int deg = min(g_cnt[v], ELL_CAP);
    const int* row = g_ell + (size_t)v * ELL_CAP;
    int j = hf;
    for (; j + 6 < deg; j += 8) {
        int s0 = __ldg(&row[j]);
        int s1 = __ldg(&row[j + 2]);
        int s2 = __ldg(&row[j + 4]);
        int s3 = __ldg(&row[j + 6]);
        uint4 u0 = __ldg(&gin4[(size_t)s0 * 16 + sub]);
        uint4 u1 = __ldg(&gin4[(size_t)s1 * 16 + sub]);
        uint4 u2 = __ldg(&gin4[(size_t)s2 * 16 + sub]);
        uint4 u3 = __ldg(&gin4[(size_t)s3 * 16 + sub]);
        acc8(a, u0); acc8(a, u1); acc8(a, u2); acc8(a, u3);
    }
    for (; j < deg; j += 2) {
        int s0 = __ldg(&row[j]);
        uint4 u0 = __ldg(&gin4[(size_t)s0 * 16 + sub]);
        acc8(a, u0);
    }
    __syncwarp();
    #pragma unroll
    for (int k = 0; k < 8; ++k) a[k] += __shfl_xor_sync(0xFFFFFFFFu, a[k], 16);
    if (hf == 0) {
        uint4 us = __ldg(&gin4[(size_t)v * 16 + sub]);   // self loop
        acc8(a, us);
        float dv = g_dinv[v];
        const float4* b4 = (const float4*)bias;
        float4 bb0 = __ldg(&b4[sub * 2]);
        float4 bb1 = __ldg(&b4[sub * 2 + 1]);
        __half2 p0 = __floats2half2_rn(fmaxf(dv * a[0] + bb0.x, 0.0f),
                                       fmaxf(dv * a[1] + bb0.y, 0.0f));
        __half2 p1 = __floats2half2_rn(fmaxf(dv * a[2] + bb0.z, 0.0f),
                                       fmaxf(dv * a[3] + bb0.w, 0.0f));
        __half2 p2 = __floats2half2_rn(fmaxf(dv * a[4] + bb1.x, 0.0f),
                                       fmaxf(dv * a[5] + bb1.y, 0.0f));
        __half2 p3 = __floats2half2_rn(fmaxf(dv * a[6] + bb1.z, 0.0f),
                                       fmaxf(dv * a[7] + bb1.w, 0.0f));
        uint4 o;
        o.x = *(const unsigned*)&p0;
        o.y = *(const unsigned*)&p1;
        o.z = *(const unsigned*)&p2;
        o.w = *(const unsigned*)&p3;
        ((uint4*)gout)[(size_t)v * 16 + sub] = o;
    }
}

// ---------------- fused pool: bounds + mean, one block per graph (R5 proven) ----------------
__global__ void k_poolmean(const __half* __restrict__ h, const void* batch,
                           float* __restrict__ outp) {
    int g = blockIdx.x;
    __shared__ int sb[2];
    if (threadIdx.x < 2) {
        int target = g + threadIdx.x;
        int lo = 0, hi = N_NODES;
        while (lo < hi) {
            int mid = (lo + hi) >> 1;
            if (load_idx(batch, mid) < target) lo = mid + 1; else hi = mid;
        }
        sb[threadIdx.x] = lo;
    }
    __syncthreads();
    int s = sb[0], e = sb[1];
    int stream = threadIdx.x >> 6;     // 16 row streams
    int c2 = threadIdx.x & 63;         // half2 column
    const __half2* h2p = (const __half2*)h;
    float2 acc = make_float2(0.0f, 0.0f);
    #pragma unroll 4
    for (int r = s + stream; r < e; r += 16) {
        float2 t = __half22float2(h2p[(size_t)r * 64 + c2]);
        acc.x += t.x; acc.y += t.y;
    }
    __shared__ float2 red[1024];
    red[threadIdx.x] = acc;
    __syncthreads();
    if (threadIdx.x < 64) {
        float2 a = make_float2(0.0f, 0.0f);
        #pragma unroll
        for (int k = 0; k < 16; ++k) {
            float2 t = red[k * 64 + threadIdx.x];
            a.x += t.x; a.y += t.y;
        }
        float inv = 1.0f / fmaxf((float)(e - s), 1.0f);
        outp[g * HID + c2 * 2]     = a.x * inv;
        outp[g * HID + c2 * 2 + 1] = a.y * inv;
    }
}

// ---------------- launch (single stream, linear chain) ----------------
extern "C" void kernel_launch(void* const* d_in, const int* in_sizes, int n_in,
                              void* d_out, int out_size) {
    const float* x  = (const float*)d_in[0];
    const void*  ei = d_in[1];
    const void*  batch = d_in[2];
    const float* W1 = (const float*)d_in[3];
    const float* b1 = (const float*)d_in[4];
    const float* W2 = (const float*)d_in[5];
    const float* b2 = (const float*)d_in[6];
    float* out = (float*)d_out;

    void* cntp;  cudaGetSymbolAddress(&cntp, g_cnt);
    void* h16Ap; cudaGetSymbolAddress(&h16Ap, g_h16A);
    void* h16Bp; cudaGetSymbolAddress(&h16Bp, g_h16B);

    static int smem_set = 0;
    const int mma_smem = HID * MM_PITCH * sizeof(__half) + 8 * 16 * MM_PITCH * sizeof(float);
    if (!smem_set) {
        cudaFuncSetAttribute(k_h2w2_mma, cudaFuncAttributeMaxDynamicSharedMemorySize, mma_smem);
        smem_set = 1;
    }

    k_detect<<<1, 64>>>((const int*)ei);
    cudaMemsetAsync(cntp, 0, N_NODES * sizeof(int));

    const int EB4 = (N_EDGES / 4 + 255) / 256;
    k_fill_ell<<<EB4, 256>>>(ei);
    k_pre<<<(N_NODES + 255) / 256, 256>>>(x);
    k_layer1<<<1184, 256>>>(W1, b1, (__half*)h16Ap);                                    // h2 -> A
    k_h2w2_mma<<<296, 256, mma_smem>>>((__half*)h16Ap, W2, (__half*)h16Bp);             // g2 -> B
    k_gather2<<<(N_NODES * 32 + 255) / 256, 256>>>((__half*)h16Bp, b2, (__half*)h16Ap); // h3 -> A
    k_poolmean<<<N_GRAPH, 1024>>>((__half*)h16Ap, batch, out);
}

// round 10
// speedup vs baseline: 1.5916x; 1.1075x over previous
#include <cuda_runtime.h>
#include <cuda_fp16.h>
#include <mma.h>
#include <stdint.h>
using namespace nvcuda;

#define N_NODES 100000
#define N_EDGES 1600000
#define N_GRAPH 64
#define HID 128
#define IN_C 4
#define ELL_CAP 64
#define N_PAD ((N_NODES + 127) & ~127)   // 100096

// ---------------- scratch ----------------
__device__ __half g_h16A[(size_t)N_PAD * HID];    // h2, then h3
__device__ __half g_h16B[(size_t)N_PAD * HID];    // g2
__device__ int    g_ell[(size_t)N_NODES * ELL_CAP];  // 25.6 MB
__device__ int    g_cnt[N_NODES];                 // in-degree (atomic cursor)
__device__ float  g_dinv[N_NODES];
__device__ float4 g_pf[N_NODES];                  // fp32x4: dinv*x
__device__ float4 g_agg[N_NODES];                 // aggregated, dinv-scaled
__device__ int    g_is64;

// ---------------- dtype detection ----------------
__global__ void k_detect(const int* ei32) {
    int t = threadIdx.x;
    int z = (ei32[2 * t + 1] == 0);
    unsigned m = __ballot_sync(0xFFFFFFFFu, z);
    __shared__ int ok[2];
    if ((t & 31) == 0) ok[t >> 5] = (m == 0xFFFFFFFFu);
    __syncthreads();
    if (t == 0) g_is64 = ok[0] & ok[1];
}

__device__ __forceinline__ int load_idx(const void* p, long long i) {
    if (g_is64) return (int)((const long long*)p)[i];
    return ((const int*)p)[i];
}

// ---------------- single-pass ELL build (4 edges / thread) ----------------
__global__ void k_fill_ell(const void* ei) {
    int t = blockIdx.x * blockDim.x + threadIdx.x;
    if (t >= N_EDGES / 4) return;
    int s[4], d[4];
    if (g_is64) {
        const longlong2* p64 = (const longlong2*)ei;
        longlong2 ps0 = __ldg(&p64[2 * t]);
        longlong2 ps1 = __ldg(&p64[2 * t + 1]);
        longlong2 pd0 = __ldg(&p64[N_EDGES / 2 + 2 * t]);
        longlong2 pd1 = __ldg(&p64[N_EDGES / 2 + 2 * t + 1]);
        s[0] = (int)ps0.x; s[1] = (int)ps0.y; s[2] = (int)ps1.x; s[3] = (int)ps1.y;
        d[0] = (int)pd0.x; d[1] = (int)pd0.y; d[2] = (int)pd1.x; d[3] = (int)pd1.y;
    } else {
        const int4* p32 = (const int4*)ei;
        int4 ps = __ldg(&p32[t]);
        int4 pd = __ldg(&p32[N_EDGES / 4 + t]);
        s[0] = ps.x; s[1] = ps.y; s[2] = ps.z; s[3] = ps.w;
        d[0] = pd.x; d[1] = pd.y; d[2] = pd.z; d[3] = pd.w;
    }
    #pragma unroll
    for (int k = 0; k < 4; ++k) {
        int pos = atomicAdd(&g_cnt[d[k]], 1);
        if (pos < ELL_CAP) g_ell[(size_t)d[k] * ELL_CAP + pos] = s[k];
    }
}

// ---------------- pre: dinv + p = fp32x4(dinv * x) ----------------
__global__ void k_pre(const float* __restrict__ x) {
    int v = blockIdx.x * blockDim.x + threadIdx.x;
    if (v >= N_NODES) return;
    float dv = rsqrtf((float)(g_cnt[v] + 1));   // +1 self loop
    g_dinv[v] = dv;
    float4 xv = __ldg(&((const float4*)x)[v]);
    float4 p;
    p.x = dv * xv.x; p.y = dv * xv.y; p.z = dv * xv.z; p.w = dv * xv.w;
    g_pf[v] = p;
}

// ---------------- layer-1 aggregation: thread per node ----------------
__global__ void k_agg1() {
    int v = blockIdx.x * blockDim.x + threadIdx.x;
    if (v >= N_NODES) return;
    int deg = min(g_cnt[v], ELL_CAP);
    const int4* row4 = (const int4*)(g_ell + (size_t)v * ELL_CAP);
    float4 acc = g_pf[v];                       // self loop
    int nq = (deg + 3) >> 2;
    for (int q = 0; q < nq; ++q) {
        int4 s = __ldg(&row4[q]);
        int base = q << 2;
        if (base + 0 < deg) { float4 t = __ldg(&g_pf[s.x]); acc.x += t.x; acc.y += t.y; acc.z += t.z; acc.w += t.w; }
        if (base + 1 < deg) { float4 t = __ldg(&g_pf[s.y]); acc.x += t.x; acc.y += t.y; acc.z += t.z; acc.w += t.w; }
        if (base + 2 < deg) { float4 t = __ldg(&g_pf[s.z]); acc.x += t.x; acc.y += t.y; acc.z += t.z; acc.w += t.w; }
        if (base + 3 < deg) { float4 t = __ldg(&g_pf[s.w]); acc.x += t.x; acc.y += t.y; acc.z += t.z; acc.w += t.w; }
    }
    float dv = g_dinv[v];
    acc.x *= dv; acc.y *= dv; acc.z *= dv; acc.w *= dv;
    g_agg[v] = acc;
}

// ---------------- layer-1 transform: warp per node, h2 = relu(agg @ W1 + b1) fp16 ----------------
__global__ void k_trans1(const float* __restrict__ W1, const float* __restrict__ b1,
                         __half* __restrict__ outh) {
    int warp = (blockIdx.x * blockDim.x + threadIdx.x) >> 5;
    int lane = threadIdx.x & 31;
    int nwarps = (gridDim.x * blockDim.x) >> 5;
    const float4* W4 = (const float4*)W1;        // row k, cols 4lane..4lane+3
    float4 w0 = __ldg(&W4[0 * 32 + lane]);
    float4 w1 = __ldg(&W4[1 * 32 + lane]);
    float4 w2 = __ldg(&W4[2 * 32 + lane]);
    float4 w3 = __ldg(&W4[3 * 32 + lane]);
    float4 bb = __ldg(&((const float4*)b1)[lane]);
    for (int v = warp; v < N_NODES; v += nwarps) {
        float av = (lane < IN_C) ? ((const float*)&g_agg[v])[lane] : 0.0f;
        float a0 = __shfl_sync(0xFFFFFFFFu, av, 0);
        float a1 = __shfl_sync(0xFFFFFFFFu, av, 1);
        float a2 = __shfl_sync(0xFFFFFFFFu, av, 2);
        float a3 = __shfl_sync(0xFFFFFFFFu, av, 3);
        float o0 = fmaxf(a0 * w0.x + a1 * w1.x + a2 * w2.x + a3 * w3.x + bb.x, 0.0f);
        float o1 = fmaxf(a0 * w0.y + a1 * w1.y + a2 * w2.y + a3 * w3.y + bb.y, 0.0f);
        float o2 = fmaxf(a0 * w0.z + a1 * w1.z + a2 * w2.z + a3 * w3.z + bb.z, 0.0f);
        float o3 = fmaxf(a0 * w0.w + a1 * w1.w + a2 * w2.w + a3 * w3.w + bb.w, 0.0f);
        __half2 p0 = __floats2half2_rn(o0, o1);
        __half2 p1 = __floats2half2_rn(o2, o3);
        uint2 u;
        u.x = *(const unsigned*)&p0;
        u.y = *(const unsigned*)&p1;
        ((uint2*)(outh + (size_t)v * HID))[lane] = u;
    }
}

// ---------------- tensor-core GEMM: g2 = fp16( dinv * (h2 @ W2) ) ----------------
#define MM_PITCH 136
__global__ void k_h2w2_mma(const __half* __restrict__ hin, const float* __restrict__ W2,
                           __half* __restrict__ outh) {
    extern __shared__ __half smh[];
    __half* W2h = smh;                                   // [128][MM_PITCH] fp16
    float* stage = (float*)(smh + HID * MM_PITCH);       // [8][16][MM_PITCH] fp32
    int t = threadIdx.x;
    int warp = t >> 5, lane = t & 31;
    for (int i = t; i < HID * HID; i += 256) {
        int r = i >> 7, c = i & 127;
        W2h[r * MM_PITCH + c] = __float2half(W2[i]);
    }
    __syncthreads();

    float* st = stage + warp * 16 * MM_PITCH;
    const int ntiles = N_PAD / 128;   // 782
    for (int tile = blockIdx.x; tile < ntiles; tile += gridDim.x) {
        int row0 = tile * 128 + warp * 16;
        wmma::fragment<wmma::accumulator, 16, 16, 16, float> c[8];
        #pragma unroll
        for (int n = 0; n < 8; ++n) wmma::fill_fragment(c[n], 0.0f);
        #pragma unroll
        for (int k0 = 0; k0 < HID; k0 += 16) {
            wmma::fragment<wmma::matrix_a, 16, 16, 16, __half, wmma::row_major> a;
            wmma::load_matrix_sync(a, hin + (size_t)row0 * HID + k0, HID);
            #pragma unroll
            for (int n = 0; n < 8; ++n) {
                wmma::fragment<wmma::matrix_b, 16, 16, 16, __half, wmma::row_major> b;
                wmma::load_matrix_sync(b, W2h + k0 * MM_PITCH + n * 16, MM_PITCH);
                wmma::mma_sync(c[n], a, b, c[n]);
            }
        }
        #pragma unroll
        for (int n = 0; n < 8; ++n)
            wmma::store_matrix_sync(st + n * 16, c[n], MM_PITCH, wmma::mem_row_major);
        __syncwarp();
        #pragma unroll
        for (int r = 0; r < 16; ++r) {
            int row = row0 + r;
            if (row < N_NODES) {
                float dv = g_dinv[row];
                float4 v = *(const float4*)&st[r * MM_PITCH + lane * 4];
                __half2 p0 = __floats2half2_rn(dv * v.x, dv * v.y);
                __half2 p1 = __floats2half2_rn(dv * v.z, dv * v.w);
                uint2 u;
                u.x = *(const unsigned*)&p0;
                u.y = *(const unsigned*)&p1;
                *(uint2*)&outh[(size_t)row * HID + lane * 4] = u;
            }
        }
        __syncwarp();
    }
}

// ---------------- layer-2 gather: h3 = relu(dinv*agg(g2) + b2), fp16 out ----------------
__device__ __forceinline__ void acc8(float* a, uint4 u) {
    float2 f0 = __half22float2(*(const __half2*)&u.x);
    float2 f1 = __half22float2(*(const __half2*)&u.y);
    float2 f2 = __half22float2(*(const __half2*)&u.z);
    float2 f3 = __half22float2(*(const __half2*)&u.w);
    a[0] += f0.x; a[1] += f0.y; a[2] += f1.x; a[3] += f1.y;
    a[4] += f2.x; a[5] += f2.y; a[6] += f3.x; a[7] += f3.y;
}

__global__ void k_gather2(const __half* __restrict__ gin, const float* __restrict__ bias,
                          __half* __restrict__ gout) {
    int v = (blockIdx.x * blockDim.x + threadIdx.x) >> 5;
    int lane = threadIdx.x & 31;
    if (v >= N_NODES) return;
    int hf = lane >> 4, sub = lane & 15;
    const uint4* gin4 = (const uint4*)gin;     // 16 uint4 per node row
    float a[8];
    #pragma unroll
    for (int k = 0; k < 8; ++k) a[k] = 0.0f;
    int deg = min(g_cnt[v], ELL_CAP);
    const int* row = g_ell + (size_t)v * ELL_CAP;
    int j = hf;
    for (; j + 6 < deg; j += 8) {
        int s0 = __ldg(&row[j]);
        int s1 = __ldg(&row[j + 2]);
        int s2 = __ldg(&row[j + 4]);
        int s3 = __ldg(&row[j + 6]);
        uint4 u0 = __ldg(&gin4[(size_t)s0 * 16 + sub]);
        uint4 u1 = __ldg(&gin4[(size_t)s1 * 16 + sub]);
        uint4 u2 = __ldg(&gin4[(size_t)s2 * 16 + sub]);
        uint4 u3 = __ldg(&gin4[(size_t)s3 * 16 + sub]);
        acc8(a, u0); acc8(a, u1); acc8(a, u2); acc8(a, u3);
    }
    for (; j < deg; j += 2) {
        int s0 = __ldg(&row[j]);
        uint4 u0 = __ldg(&gin4[(size_t)s0 * 16 + sub]);
        acc8(a, u0);
    }
    __syncwarp();
    #pragma unroll
    for (int k = 0; k < 8; ++k) a[k] += __shfl_xor_sync(0xFFFFFFFFu, a[k], 16);
    if (hf == 0) {
        uint4 us = __ldg(&gin4[(size_t)v * 16 + sub]);   // self loop
        acc8(a, us);
        float dv = g_dinv[v];
        const float4* b4 = (const float4*)bias;
        float4 bb0 = __ldg(&b4[sub * 2]);
        float4 bb1 = __ldg(&b4[sub * 2 + 1]);
        __half2 p0 = __floats2half2_rn(fmaxf(dv * a[0] + bb0.x, 0.0f),
                                       fmaxf(dv * a[1] + bb0.y, 0.0f));
        __half2 p1 = __floats2half2_rn(fmaxf(dv * a[2] + bb0.z, 0.0f),
                                       fmaxf(dv * a[3] + bb0.w, 0.0f));
        __half2 p2 = __floats2half2_rn(fmaxf(dv * a[4] + bb1.x, 0.0f),
                                       fmaxf(dv * a[5] + bb1.y, 0.0f));
        __half2 p3 = __floats2half2_rn(fmaxf(dv * a[6] + bb1.z, 0.0f),
                                       fmaxf(dv * a[7] + bb1.w, 0.0f));
        uint4 o;
        o.x = *(const unsigned*)&p0;
        o.y = *(const unsigned*)&p1;
        o.z = *(const unsigned*)&p2;
        o.w = *(const unsigned*)&p3;
        ((uint4*)gout)[(size_t)v * 16 + sub] = o;
    }
}

// ---------------- fused pool: bounds + mean, one block per graph ----------------
__global__ void k_poolmean(const __half* __restrict__ h, const void* batch,
                           float* __restrict__ outp) {
    int g = blockIdx.x;
    __shared__ int sb[2];
    if (threadIdx.x < 2) {
        int target = g + threadIdx.x;
        int lo = 0, hi = N_NODES;
        while (lo < hi) {
            int mid = (lo + hi) >> 1;
            if (load_idx(batch, mid) < target) lo = mid + 1; else hi = mid;
        }
        sb[threadIdx.x] = lo;
    }
    __syncthreads();
    int s = sb[0], e = sb[1];
    int stream = threadIdx.x >> 6;     // 16 row streams
    int c2 = threadIdx.x & 63;         // half2 column
    const __half2* h2p = (const __half2*)h;
    float2 acc = make_float2(0.0f, 0.0f);
    #pragma unroll 4
    for (int r = s + stream; r < e; r += 16) {
        float2 t = __half22float2(h2p[(size_t)r * 64 + c2]);
        acc.x += t.x; acc.y += t.y;
    }
    __shared__ float2 red[1024];
    red[threadIdx.x] = acc;
    __syncthreads();
    if (threadIdx.x < 64) {
        float2 a = make_float2(0.0f, 0.0f);
        #pragma unroll
        for (int k = 0; k < 16; ++k) {
            float2 t = red[k * 64 + threadIdx.x];
            a.x += t.x; a.y += t.y;
        }
        float inv = 1.0f / fmaxf((float)(e - s), 1.0f);
        outp[g * HID + c2 * 2]     = a.x * inv;
        outp[g * HID + c2 * 2 + 1] = a.y * inv;
    }
}

// ---------------- launch (single stream, linear chain) ----------------
extern "C" void kernel_launch(void* const* d_in, const int* in_sizes, int n_in,
                              void* d_out, int out_size) {
    const float* x  = (const float*)d_in[0];
    const void*  ei = d_in[1];
    const void*  batch = d_in[2];
    const float* W1 = (const float*)d_in[3];
    const float* b1 = (const float*)d_in[4];
    const float* W2 = (const float*)d_in[5];
    const float* b2 = (const float*)d_in[6];
    float* out = (float*)d_out;

    void* cntp;  cudaGetSymbolAddress(&cntp, g_cnt);
    void* h16Ap; cudaGetSymbolAddress(&h16Ap, g_h16A);
    void* h16Bp; cudaGetSymbolAddress(&h16Bp, g_h16B);

    static int smem_set = 0;
    const int mma_smem = HID * MM_PITCH * sizeof(__half) + 8 * 16 * MM_PITCH * sizeof(float);
    if (!smem_set) {
        cudaFuncSetAttribute(k_h2w2_mma, cudaFuncAttributeMaxDynamicSharedMemorySize, mma_smem);
        smem_set = 1;
    }

    k_detect<<<1, 64>>>((const int*)ei);
    cudaMemsetAsync(cntp, 0, N_NODES * sizeof(int));

    const int EB4 = (N_EDGES / 4 + 255) / 256;
    k_fill_ell<<<EB4, 256>>>(ei);
    k_pre<<<(N_NODES + 255) / 256, 256>>>(x);
    k_agg1<<<(N_NODES + 255) / 256, 256>>>();
    k_trans1<<<592, 256>>>(W1, b1, (__half*)h16Ap);                                     // h2 -> A
    k_h2w2_mma<<<296, 256, mma_smem>>>((__half*)h16Ap, W2, (__half*)h16Bp);             // g2 -> B
    k_gather2<<<(N_NODES * 32 + 255) / 256, 256>>>((__half*)h16Bp, b2, (__half*)h16Ap); // h3 -> A
    k_poolmean<<<N_GRAPH, 1024>>>((__half*)h16Ap, batch, out);
}